// round 15
// baseline (speedup 1.0000x reference)
#include <cuda_runtime.h>
#include <cuda_bf16.h>
#include <cstdint>

// ---------------------------------------------------------------------------
// StackRNN v15 = v12 (best: 740.1us) + two subtractive tweaks:
//  (1) mem warp reuses its pre-dot Z reciprocal for invZm (drops a redundant
//      LDS.128 + adds + rcp from the slowest warp);
//  (2) B slot-ring deepened 4 -> 6 (ready ids 2-7, free ids 8-13) so A's
//      free-slot backpressure starts at t>=5 instead of t>=3.
//
// Group A (warps 0-7, 256 thr): 4 state + 2 mem + 2 update warps. One
//   bar.sync(1,256) per step. Writes per-step slots into a DEPTH-6 ring.
// Group B (warps 8-15, 256 thr): buffer-logit warps, lag <=5 steps behind.
// ---------------------------------------------------------------------------

#define NOUT 210
#define B_TOT 256
#define SEQ 1024
#define NTHREADS 512
#define NSLOT 6

#define BAR_SYNC(id, cnt)   asm volatile("bar.sync %0, %1;"   :: "r"(id), "r"(cnt) : "memory")
#define BAR_ARRIVE(id, cnt) asm volatile("bar.arrive %0, %1;" :: "r"(id), "r"(cnt) : "memory")

typedef unsigned long long ull;

__device__ __forceinline__ ull ffma2(ull a, ull b, ull c) {
    ull d; asm("fma.rn.f32x2 %0,%1,%2,%3;" : "=l"(d) : "l"(a), "l"(b), "l"(c)); return d;
}
__device__ __forceinline__ ull fadd2(ull a, ull b) {
    ull d; asm("add.rn.f32x2 %0,%1,%2;" : "=l"(d) : "l"(a), "l"(b)); return d;
}
__device__ __forceinline__ ull pack2(float lo, float hi) {
    ull d; asm("mov.b64 %0,{%1,%2};" : "=l"(d) : "f"(lo), "f"(hi)); return d;
}
__device__ __forceinline__ float lo2(ull v) { return __uint_as_float((unsigned)v); }
__device__ __forceinline__ float hi2(ull v) { return __uint_as_float((unsigned)(v >> 32)); }

__device__ __align__(16) float g_E[128 * NOUT];
__device__ __align__(16) float g_CW[80 * NOUT];
__device__ __align__(16) float g_c[NOUT];

// ---------------- fast precompute (bench-verified in v12) ----------------
__global__ void precompute_kernel(
    const float* __restrict__ embed,
    const float* __restrict__ w_state, const float* __restrict__ b_state,
    const float* __restrict__ w_top,   const float* __restrict__ b_top,
    const float* __restrict__ w_mem,   const float* __restrict__ b_mem,
    const float* __restrict__ w_buf,   const float* __restrict__ b_buf,
    const float* __restrict__ w_st,    const float* __restrict__ b_st)
{
    __shared__ __align__(16) float wcol[768];
    int n = blockIdx.x;
    const float* W; const float* bias; int N, col;
    if (n < 64)       { W = w_st;  bias = b_st;  N = 64;  col = n; }
    else if (n < 82)  { W = w_mem; bias = b_mem; N = 18;  col = n - 64; }
    else              { W = w_buf; bias = b_buf; N = 128; col = n - 82; }

    const int tid = threadIdx.x;
    for (int i = tid; i < 768; i += 448) wcol[i] = W[i * N + col];
    __syncthreads();

    float sp = 0.f;
    if (tid < 256) {
        int row = tid >> 1, half = tid & 1;
        const float4* er = (const float4*)(embed + row * 256 + half * 128);
        const float4* wc = (const float4*)(wcol + half * 128);
        float s0 = 0.f, s1 = 0.f, s2 = 0.f, s3 = 0.f;
#pragma unroll 8
        for (int h = 0; h < 32; h++) {
            float4 e = er[h], w4 = wc[h];
            s0 += e.x * w4.x; s1 += e.y * w4.y;
            s2 += e.z * w4.z; s3 += e.w * w4.w;
        }
        sp = (s0 + s1) + (s2 + s3);
    } else if (tid < 384) {
        int r = (tid - 256) >> 1, half = tid & 1;
        const float4* wr = (const float4*)(w_state + r * 256 + half * 128);
        const float4* wc = (const float4*)(wcol + 256 + half * 128);
        float s0 = 0.f, s1 = 0.f, s2 = 0.f, s3 = 0.f;
#pragma unroll 8
        for (int h = 0; h < 32; h++) {
            float4 e = wr[h], w4 = wc[h];
            s0 += e.x * w4.x; s1 += e.y * w4.y;
            s2 += e.z * w4.z; s3 += e.w * w4.w;
        }
        sp = (s0 + s1) + (s2 + s3);
    } else if (tid < 416) {
        int r = (tid - 384) >> 1, half = tid & 1;
        const float4* wr = (const float4*)(w_top + r * 256 + half * 128);
        const float4* wc = (const float4*)(wcol + 512 + half * 128);
        float s0 = 0.f, s1 = 0.f, s2 = 0.f, s3 = 0.f;
#pragma unroll 8
        for (int h = 0; h < 32; h++) {
            float4 e = wr[h], w4 = wc[h];
            s0 += e.x * w4.x; s1 += e.y * w4.y;
            s2 += e.z * w4.z; s3 += e.w * w4.w;
        }
        sp = (s0 + s1) + (s2 + s3);
    } else {
        int lane = tid - 416;
        const float4* bs = (const float4*)b_state;
        const float4* bt = (const float4*)b_top;
        const float4* wc = (const float4*)(wcol + 256);
#pragma unroll
        for (int j = 0; j < 4; j++) {
            int k = lane + j * 32;
            float4 b4 = (k < 64) ? bs[k] : bt[k - 64];
            float4 w4 = wc[k];
            sp += b4.x * w4.x + b4.y * w4.y + b4.z * w4.z + b4.w * w4.w;
        }
        float t = sp;
        for (int o = 16; o; o >>= 1) t += __shfl_xor_sync(0xffffffffu, t, o);
        if (lane == 0) g_c[n] = t + bias[col];
    }

    float pair = sp + __shfl_xor_sync(0xffffffffu, sp, 1);
    if ((tid & 1) == 0) {
        if (tid < 256)      g_E[(tid >> 1) * NOUT + n] = pair;
        else if (tid < 384) g_CW[((tid - 256) >> 1) * NOUT + n] = pair;
        else if (tid < 416) g_CW[(64 + ((tid - 384) >> 1)) * NOUT + n] = pair;
    }
}

// Shared floats:
//   sE     @ 0     : 26880            [tok][n]
//   sTok   @ 26880 : 2048 ints        [g][t]
//   sStack @ 28928 : [ping][g][64][16] = 4096   (depth 2, A-only)
//   sSt    @ 33024 : [slot][g][64] = 768        raw state exps (depth 6)
//   sZs    @ 33792 : [slot][g][16] = 192        state Z partials (depth 6)
//   sTop   @ 33984 : [slot][g][16] = 192        raw top~ (depth 6)
//   sZmP   @ 34176 : [slot][g][8]  = 96         mem Z partials (depth 6)
//   sPr    @ 34272 : [ping][g][20] = 80         raw probs (depth 2, A-only)
#define SMEM_FLOATS 34352

__device__ __forceinline__ void stack_update(const float* pr, const float* zmp,
                                             const float* P, float* Q, int lane)
{
    float pe0 = pr[0], pe1 = pr[1];
    float4 za = *(const float4*)zmp;
    float4 zb = *(const float4*)(zmp + 4);
    float Zr = ((za.x + za.y) + (za.z + za.w)) + ((zb.x + zb.y) + (zb.z + zb.w));
    float iz = __fdividef(1.f, Zr);
    float ppop  = pe0 * iz;
    float pnoop = pe1 * iz;
    float ppush = (Zr - pe0 - pe1) * iz;
    const int c = lane & 3;
    const int d0 = (lane >> 2) * 8;
    float4 pv = ((const float4*)(pr + 4))[c];
    pv.x *= iz; pv.y *= iz; pv.z *= iz; pv.w *= iz;

    const float4* P4 = (const float4*)P;
    float4*       Q4 = (float4*)Q;
    float4 prev = (d0 == 0) ? make_float4(0.f, 0.f, 0.f, 0.f) : P4[(d0 - 1) * 4 + c];
    float4 cur  = P4[d0 * 4 + c];
#pragma unroll
    for (int i = 0; i < 8; i++) {
        int d = d0 + i;
        float4 nxt;
        if (d == 63) nxt = (c == 0) ? make_float4(1.f, 0.f, 0.f, 0.f)
                                    : make_float4(0.f, 0.f, 0.f, 0.f);
        else         nxt = P4[(d + 1) * 4 + c];
        float4 o;
        o.x = ppush * prev.x + ppop * nxt.x + pnoop * cur.x;
        o.y = ppush * prev.y + ppop * nxt.y + pnoop * cur.y;
        o.z = ppush * prev.z + ppop * nxt.z + pnoop * cur.z;
        o.w = ppush * prev.w + ppop * nxt.w + pnoop * cur.w;
        if (d == 0) { o.x += pv.x; o.y += pv.y; o.z += pv.z; o.w += pv.w; }
        Q4[d * 4 + c] = o;
        prev = cur; cur = nxt;
    }
}

__global__ __launch_bounds__(NTHREADS, 1)
void stackrnn_kernel(const int* __restrict__ x, float* __restrict__ out)
{
    extern __shared__ float sm[];
    float* sE     = sm;
    int*   sTok   = (int*)(sm + 26880);
    float* sStack = sm + 28928;
    float* sSt    = sm + 33024;
    float* sZs    = sm + 33792;
    float* sTop   = sm + 33984;
    float* sZmP   = sm + 34176;
    float* sPr    = sm + 34272;

    const int tid  = threadIdx.x;
    const int wid  = tid >> 5;
    const int lane = tid & 31;
    const int b0   = blockIdx.x * 2;

    // ---- one-time setup ----
    {
        const float4* src = (const float4*)g_E;
        float4* dst = (float4*)sE;
        for (int i = tid; i < (128 * NOUT) / 4; i += NTHREADS) dst[i] = src[i];
    }
    for (int i = tid; i < 2 * SEQ; i += NTHREADS) {
        int g = i >> 10, r = i & 1023;
        sTok[i] = x[(size_t)(b0 + g) * SEQ + r];
    }
    for (int i = tid; i < 2048; i += NTHREADS) sStack[i] = ((i & 15) == 0) ? 1.f : 0.f;
    if (tid < 128) sSt[tid] = 0.f;                            // slot 0
    if (tid < 32)  sZs[tid]  = 0.0625f;                       // slot 0: sums to 1
    if (tid < 32)  sTop[tid] = (tid == 0 || tid == 16) ? 1.f : 0.f;
    if (tid < 16)  sZmP[tid] = (tid == 0 || tid == 8) ? 1.f : 0.f;
    if (tid < 40)  sPr[tid]  = (tid == 1 || tid == 21) ? 1.f : 0.f;  // noop=1

    // ---- roles ----
    const bool isState  = (wid < 4);
    const bool isMem    = (wid == 4 || wid == 5);
    const bool isUpdate = (wid == 6 || wid == 7);
    const bool isBuf    = (wid >= 8);
    int g, mycol;
    if (isState)       { g = wid >> 1;  mycol = (wid & 1) * 32 + lane; }
    else if (isMem)    { g = wid - 4;   mycol = 64 + (lane < 18 ? lane : 0); }
    else if (isUpdate) { g = wid - 6;   mycol = 0; }
    else               { int idx = tid - 256; g = idx >> 7; mycol = 82 + (idx & 127); }

    ull W[40];
    float cn = 0.f;
    if (!isUpdate) {
        cn = g_c[mycol];
#pragma unroll
        for (int k = 0; k < 40; k++)
            W[k] = pack2(g_CW[(2 * k) * NOUT + mycol], g_CW[(2 * k + 1) * NOUT + mycol]);
    }
    __syncthreads();

    if (isBuf) {
        // =================== GROUP B: buffer logits, lagged ===================
        const size_t outB = (size_t)(b0 + g) * (SEQ * 128);
        float baseNext = cn + sE[sTok[g * SEQ] * NOUT + mycol];
        int sCur = 0;
        for (int t = 0; t < SEQ; t++) {
            BAR_SYNC(2 + sCur, 512);          // wait slot ready

            const ulonglong2* ZS = (const ulonglong2*)(sZs + sCur * 32 + g * 16);
            ulonglong2 z0 = ZS[0], z1 = ZS[1], z2 = ZS[2], z3 = ZS[3];
            ull zz = fadd2(fadd2(fadd2(z0.x, z0.y), fadd2(z1.x, z1.y)),
                           fadd2(fadd2(z2.x, z2.y), fadd2(z3.x, z3.y)));
            const float invZs = __fdividef(1.f, lo2(zz) + hi2(zz));
            const ulonglong2* ZM = (const ulonglong2*)(sZmP + sCur * 16 + g * 8);
            ulonglong2 m0 = ZM[0], m1 = ZM[1];
            ull mm = fadd2(fadd2(m0.x, m0.y), fadd2(m1.x, m1.y));
            const float invZm = __fdividef(1.f, lo2(mm) + hi2(mm));
            const float base = baseNext;

            const ulonglong2* S = (const ulonglong2*)(sSt + sCur * 128 + g * 64);
            ull a0 = 0, a1 = 0, a2 = 0, a3 = 0;
#pragma unroll
            for (int i = 0; i < 8; i++) {
                ulonglong2 p = S[2 * i], q = S[2 * i + 1];
                a0 = ffma2(W[4 * i + 0], p.x, a0);
                a1 = ffma2(W[4 * i + 1], p.y, a1);
                a2 = ffma2(W[4 * i + 2], q.x, a2);
                a3 = ffma2(W[4 * i + 3], q.y, a3);
            }
            const ulonglong2* T = (const ulonglong2*)(sTop + sCur * 32 + g * 16);
            ulonglong2 t0 = T[0], t1 = T[1], t2 = T[2], t3 = T[3];
            ull u0 = ffma2(W[32], t0.x, 0ULL), u1 = ffma2(W[33], t0.y, 0ULL);
            ull u2 = ffma2(W[34], t1.x, 0ULL), u3 = ffma2(W[35], t1.y, 0ULL);
            u0 = ffma2(W[36], t2.x, u0);  u1 = ffma2(W[37], t2.y, u1);
            u2 = ffma2(W[38], t3.x, u2);  u3 = ffma2(W[39], t3.y, u3);

            ull A = fadd2(fadd2(a0, a1), fadd2(a2, a3));
            ull U = fadd2(fadd2(u0, u1), fadd2(u2, u3));
            const float r = base + invZs * (lo2(A) + hi2(A)) + invZm * (lo2(U) + hi2(U));
            out[outB + (size_t)t * 128 + (mycol - 82)] = r;

            if (t + 1 < SEQ)
                baseNext = cn + sE[sTok[g * SEQ + t + 1] * NOUT + mycol];
            BAR_ARRIVE(8 + sCur, 512);        // release slot
            sCur = (sCur == NSLOT - 1) ? 0 : sCur + 1;
        }
    } else {
        // =================== GROUP A: recurrence ===================
        // mem-warp carried regs (lanes 0..15 hold vocab component v=lane)
        float h0 = 0.f, h1 = 0.f, h2 = 0.f;      // normalized rows of current stack
        float topc = 0.f;                         // raw row0 of next stack
        float cE0 = 0.f, cE1 = 1.f, cZp = 0.125f; // probs_{-1}=noop; Z partial
        if (isMem && lane == 0) { h0 = h1 = h2 = 1.f; topc = 1.f; }

        float baseNext = 0.f;
        if (!isUpdate) baseNext = cn + sE[sTok[g * SEQ] * NOUT + mycol];

        BAR_ARRIVE(2 + 0, 512);                   // slot 0 (initial state) ready

        int sCur = 0, sNext = 1;
        for (int t = 0; t < SEQ; t++) {
            const int ping = t & 1;
            if (t >= NSLOT - 1) BAR_SYNC(8 + sNext, 512);  // B freed slot we rewrite

            if (isUpdate) {
                stack_update(sPr + ping * 40 + g * 20, sZmP + sCur * 16 + g * 8,
                             sStack + ping * 2048 + g * 1024,
                             sStack + (ping ^ 1) * 2048 + g * 1024, lane);
            } else {
                // mem pre-dot: finish deferred Z + head rows (overlaps dot loads)
                float izp = 0.f;
                if (isMem) {
                    float Zp = cZp;
                    Zp += __shfl_xor_sync(0xffffffffu, Zp, 4);
                    Zp += __shfl_xor_sync(0xffffffffu, Zp, 8);
                    Zp += __shfl_xor_sync(0xffffffffu, Zp, 16);
                    izp = __fdividef(1.f, Zp);
                    float nh0 = topc * izp;
                    float nh1 = ((Zp - cE0 - cE1) * h0 + cE0 * h2 + cE1 * h1) * izp;
                    float s1 = 0.f, s2 = 0.f, s3 = 0.f;
                    const float* SB = sStack + ping * 2048 + g * 1024;
                    if (lane < 16) { s1 = SB[16 + lane]; s2 = SB[32 + lane]; s3 = SB[48 + lane]; }
                    float nh2 = ((Zp - cE0 - cE1) * s1 + cE0 * s3 + cE1 * s2) * izp;
                    h0 = nh0; h1 = nh1; h2 = nh2;
                }

                const ulonglong2* ZS = (const ulonglong2*)(sZs + sCur * 32 + g * 16);
                ulonglong2 z0 = ZS[0], z1 = ZS[1], z2 = ZS[2], z3 = ZS[3];
                ull zz = fadd2(fadd2(fadd2(z0.x, z0.y), fadd2(z1.x, z1.y)),
                               fadd2(fadd2(z2.x, z2.y), fadd2(z3.x, z3.y)));
                const float invZs = __fdividef(1.f, lo2(zz) + hi2(zz));
                float invZm;
                if (isMem) {
                    invZm = izp;                  // same Z as the pre-dot reduce
                } else {
                    const ulonglong2* ZM = (const ulonglong2*)(sZmP + sCur * 16 + g * 8);
                    ulonglong2 m0 = ZM[0], m1 = ZM[1];
                    ull mm = fadd2(fadd2(m0.x, m0.y), fadd2(m1.x, m1.y));
                    invZm = __fdividef(1.f, lo2(mm) + hi2(mm));
                }
                const float base = baseNext;

                const ulonglong2* S = (const ulonglong2*)(sSt + sCur * 128 + g * 64);
                ull a0 = 0, a1 = 0, a2 = 0, a3 = 0;
#pragma unroll
                for (int i = 0; i < 8; i++) {
                    ulonglong2 p = S[2 * i], q = S[2 * i + 1];
                    a0 = ffma2(W[4 * i + 0], p.x, a0);
                    a1 = ffma2(W[4 * i + 1], p.y, a1);
                    a2 = ffma2(W[4 * i + 2], q.x, a2);
                    a3 = ffma2(W[4 * i + 3], q.y, a3);
                }
                const ulonglong2* T = (const ulonglong2*)(sTop + sCur * 32 + g * 16);
                ulonglong2 t0 = T[0], t1 = T[1], t2 = T[2], t3 = T[3];
                ull u0 = ffma2(W[32], t0.x, 0ULL), u1 = ffma2(W[33], t0.y, 0ULL);
                ull u2 = ffma2(W[34], t1.x, 0ULL), u3 = ffma2(W[35], t1.y, 0ULL);
                u0 = ffma2(W[36], t2.x, u0);  u1 = ffma2(W[37], t2.y, u1);
                u2 = ffma2(W[38], t3.x, u2);  u3 = ffma2(W[39], t3.y, u3);

                ull A = fadd2(fadd2(a0, a1), fadd2(a2, a3));
                ull U = fadd2(fadd2(u0, u1), fadd2(u2, u3));
                const float r = base + invZs * (lo2(A) + hi2(A)) + invZm * (lo2(U) + hi2(U));

                if (t + 1 < SEQ)
                    baseNext = cn + sE[sTok[g * SEQ + t + 1] * NOUT + mycol];

                if (isState) {
                    float e = __expf(r);
                    sSt[sNext * 128 + g * 64 + mycol] = e;
                    float ps = e;
                    ps += __shfl_xor_sync(0xffffffffu, ps, 1);
                    ps += __shfl_xor_sync(0xffffffffu, ps, 2);
                    if ((lane & 3) == 0)
                        sZs[sNext * 32 + g * 16 + (wid & 1) * 8 + (lane >> 2)] = ps;
                } else {  // mem
                    float e = (lane < 18) ? __expf(r) : 0.f;
                    float E0 = __shfl_sync(0xffffffffu, e, 0);
                    float E1 = __shfl_sync(0xffffffffu, e, 1);
                    float ep = __shfl_sync(0xffffffffu, e, 2 + (lane & 15));
                    float topn = E1 * h0 + E0 * h1 + ep;          // raw, scale Zt
                    if (lane < 16) sTop[sNext * 32 + g * 16 + lane] = topn;
                    int pidx = (lane < 2) ? lane : lane + 2;
                    if (lane < 18) sPr[(ping ^ 1) * 40 + g * 20 + pidx] = e;
                    float pz = e;
                    pz += __shfl_xor_sync(0xffffffffu, pz, 1);
                    pz += __shfl_xor_sync(0xffffffffu, pz, 2);
                    if ((lane & 3) == 0) sZmP[sNext * 16 + g * 8 + (lane >> 2)] = pz;
                    topc = topn; cE0 = E0; cE1 = E1; cZp = pz;
                }
            }
            BAR_ARRIVE(2 + sNext, 512);   // slot sNext ready for B (after own writes)
            BAR_SYNC(1, 256);             // A-internal step barrier
            sCur = sNext; sNext = (sNext == NSLOT - 1) ? 0 : sNext + 1;
        }

        // epilogue: apply probs_{S-1} -> stack_S
        // (probs at sPr ping 0; Z at slot SEQ%6 == 4 == sCur after the loop)
        if (isUpdate) {
            stack_update(sPr + 0 * 40 + g * 20, sZmP + sCur * 16 + g * 8,
                         sStack + 0 * 2048 + g * 1024,
                         sStack + 1 * 2048 + g * 1024, lane);
        }
    }
    __syncthreads();

    // ---- finals ----  (last state/Z written into slot SEQ%6 == 4)
    const int slotF = SEQ % NSLOT;
    const size_t fsOff = (size_t)B_TOT * SEQ * 128;
    const size_t stOff = fsOff + (size_t)B_TOT * 64 * 16;
    for (int i = tid; i < 2048; i += NTHREADS) {
        int gg = i >> 10, r = i & 1023;
        out[fsOff + (size_t)(b0 + gg) * 1024 + r] = sStack[2048 + i];
    }
    if (tid < 128) {
        int gg = tid >> 6;
        float zs = 0.f;
        for (int j = 0; j < 16; j++) zs += sZs[slotF * 32 + gg * 16 + j];
        out[stOff + (size_t)(b0 + gg) * 64 + (tid & 63)] =
            sSt[slotF * 128 + gg * 64 + (tid & 63)] * __fdividef(1.f, zs);
    }
}

extern "C" void kernel_launch(void* const* d_in, const int* in_sizes, int n_in,
                              void* d_out, int out_size)
{
    const int*   x       = (const int*)  d_in[0];
    const float* embed   = (const float*)d_in[1];
    const float* w_state = (const float*)d_in[2];
    const float* b_state = (const float*)d_in[3];
    const float* w_top   = (const float*)d_in[4];
    const float* b_top   = (const float*)d_in[5];
    const float* w_mem   = (const float*)d_in[6];
    const float* b_mem   = (const float*)d_in[7];
    const float* w_buf   = (const float*)d_in[8];
    const float* b_buf   = (const float*)d_in[9];
    const float* w_st    = (const float*)d_in[10];
    const float* b_st    = (const float*)d_in[11];
    float* out = (float*)d_out;

    precompute_kernel<<<NOUT, 448>>>(embed, w_state, b_state, w_top, b_top,
                                     w_mem, b_mem, w_buf, b_buf, w_st, b_st);

    cudaFuncSetAttribute(stackrnn_kernel,
                         cudaFuncAttributeMaxDynamicSharedMemorySize,
                         SMEM_FLOATS * sizeof(float));
    stackrnn_kernel<<<B_TOT / 2, NTHREADS, SMEM_FLOATS * sizeof(float)>>>(x, out);
}

// round 16
// speedup vs baseline: 1.0664x; 1.0664x over previous
#include <cuda_runtime.h>
#include <cuda_bf16.h>
#include <cstdint>

// ---------------------------------------------------------------------------
// StackRNN v16: per-batch CTAs, 2 CTAs/SM for cross-CTA latency hiding.
// Grid 256 x 256 thr (8 warps): state wid 0-1, mem wid 2, update wid 3,
// buf wid 4-7. Exact v12 slot-ring protocol (depth 4; ready ids 2+s,
// free ids 6+s, A-internal bar 1) with the batch dimension removed.
// E table read from global (L2-resident) with one-step prefetch; smem ~14KB
// so two CTAs co-reside per SM (__launch_bounds__(256,2), regs<=128).
// ---------------------------------------------------------------------------

#define NOUT 210
#define B_TOT 256
#define SEQ 1024

#define BAR_SYNC(id, cnt)   asm volatile("bar.sync %0, %1;"   :: "r"(id), "r"(cnt) : "memory")
#define BAR_ARRIVE(id, cnt) asm volatile("bar.arrive %0, %1;" :: "r"(id), "r"(cnt) : "memory")

typedef unsigned long long ull;

__device__ __forceinline__ ull ffma2(ull a, ull b, ull c) {
    ull d; asm("fma.rn.f32x2 %0,%1,%2,%3;" : "=l"(d) : "l"(a), "l"(b), "l"(c)); return d;
}
__device__ __forceinline__ ull fadd2(ull a, ull b) {
    ull d; asm("add.rn.f32x2 %0,%1,%2;" : "=l"(d) : "l"(a), "l"(b)); return d;
}
__device__ __forceinline__ ull pack2(float lo, float hi) {
    ull d; asm("mov.b64 %0,{%1,%2};" : "=l"(d) : "f"(lo), "f"(hi)); return d;
}
__device__ __forceinline__ float lo2(ull v) { return __uint_as_float((unsigned)v); }
__device__ __forceinline__ float hi2(ull v) { return __uint_as_float((unsigned)(v >> 32)); }

__device__ __align__(16) float g_E[128 * NOUT];
__device__ __align__(16) float g_CW[80 * NOUT];
__device__ __align__(16) float g_c[NOUT];

// ---------------- fast precompute (bench-verified in v12) ----------------
__global__ void precompute_kernel(
    const float* __restrict__ embed,
    const float* __restrict__ w_state, const float* __restrict__ b_state,
    const float* __restrict__ w_top,   const float* __restrict__ b_top,
    const float* __restrict__ w_mem,   const float* __restrict__ b_mem,
    const float* __restrict__ w_buf,   const float* __restrict__ b_buf,
    const float* __restrict__ w_st,    const float* __restrict__ b_st)
{
    __shared__ __align__(16) float wcol[768];
    int n = blockIdx.x;
    const float* W; const float* bias; int N, col;
    if (n < 64)       { W = w_st;  bias = b_st;  N = 64;  col = n; }
    else if (n < 82)  { W = w_mem; bias = b_mem; N = 18;  col = n - 64; }
    else              { W = w_buf; bias = b_buf; N = 128; col = n - 82; }

    const int tid = threadIdx.x;
    for (int i = tid; i < 768; i += 448) wcol[i] = W[i * N + col];
    __syncthreads();

    float sp = 0.f;
    if (tid < 256) {
        int row = tid >> 1, half = tid & 1;
        const float4* er = (const float4*)(embed + row * 256 + half * 128);
        const float4* wc = (const float4*)(wcol + half * 128);
        float s0 = 0.f, s1 = 0.f, s2 = 0.f, s3 = 0.f;
#pragma unroll 8
        for (int h = 0; h < 32; h++) {
            float4 e = er[h], w4 = wc[h];
            s0 += e.x * w4.x; s1 += e.y * w4.y;
            s2 += e.z * w4.z; s3 += e.w * w4.w;
        }
        sp = (s0 + s1) + (s2 + s3);
    } else if (tid < 384) {
        int r = (tid - 256) >> 1, half = tid & 1;
        const float4* wr = (const float4*)(w_state + r * 256 + half * 128);
        const float4* wc = (const float4*)(wcol + 256 + half * 128);
        float s0 = 0.f, s1 = 0.f, s2 = 0.f, s3 = 0.f;
#pragma unroll 8
        for (int h = 0; h < 32; h++) {
            float4 e = wr[h], w4 = wc[h];
            s0 += e.x * w4.x; s1 += e.y * w4.y;
            s2 += e.z * w4.z; s3 += e.w * w4.w;
        }
        sp = (s0 + s1) + (s2 + s3);
    } else if (tid < 416) {
        int r = (tid - 384) >> 1, half = tid & 1;
        const float4* wr = (const float4*)(w_top + r * 256 + half * 128);
        const float4* wc = (const float4*)(wcol + 512 + half * 128);
        float s0 = 0.f, s1 = 0.f, s2 = 0.f, s3 = 0.f;
#pragma unroll 8
        for (int h = 0; h < 32; h++) {
            float4 e = wr[h], w4 = wc[h];
            s0 += e.x * w4.x; s1 += e.y * w4.y;
            s2 += e.z * w4.z; s3 += e.w * w4.w;
        }
        sp = (s0 + s1) + (s2 + s3);
    } else {
        int lane = tid - 416;
        const float4* bs = (const float4*)b_state;
        const float4* bt = (const float4*)b_top;
        const float4* wc = (const float4*)(wcol + 256);
#pragma unroll
        for (int j = 0; j < 4; j++) {
            int k = lane + j * 32;
            float4 b4 = (k < 64) ? bs[k] : bt[k - 64];
            float4 w4 = wc[k];
            sp += b4.x * w4.x + b4.y * w4.y + b4.z * w4.z + b4.w * w4.w;
        }
        float t = sp;
        for (int o = 16; o; o >>= 1) t += __shfl_xor_sync(0xffffffffu, t, o);
        if (lane == 0) g_c[n] = t + bias[col];
    }

    float pair = sp + __shfl_xor_sync(0xffffffffu, sp, 1);
    if ((tid & 1) == 0) {
        if (tid < 256)      g_E[(tid >> 1) * NOUT + n] = pair;
        else if (tid < 384) g_CW[((tid - 256) >> 1) * NOUT + n] = pair;
        else if (tid < 416) g_CW[(64 + ((tid - 384) >> 1)) * NOUT + n] = pair;
    }
}

__device__ __forceinline__ void stack_update(const float* pr, const float* zmp,
                                             const float* P, float* Q, int lane)
{
    float pe0 = pr[0], pe1 = pr[1];
    float4 za = *(const float4*)zmp;
    float4 zb = *(const float4*)(zmp + 4);
    float Zr = ((za.x + za.y) + (za.z + za.w)) + ((zb.x + zb.y) + (zb.z + zb.w));
    float iz = __fdividef(1.f, Zr);
    float ppop  = pe0 * iz;
    float pnoop = pe1 * iz;
    float ppush = (Zr - pe0 - pe1) * iz;
    const int c = lane & 3;
    const int d0 = (lane >> 2) * 8;
    float4 pv = ((const float4*)(pr + 4))[c];
    pv.x *= iz; pv.y *= iz; pv.z *= iz; pv.w *= iz;

    const float4* P4 = (const float4*)P;
    float4*       Q4 = (float4*)Q;
    float4 prev = (d0 == 0) ? make_float4(0.f, 0.f, 0.f, 0.f) : P4[(d0 - 1) * 4 + c];
    float4 cur  = P4[d0 * 4 + c];
#pragma unroll
    for (int i = 0; i < 8; i++) {
        int d = d0 + i;
        float4 nxt;
        if (d == 63) nxt = (c == 0) ? make_float4(1.f, 0.f, 0.f, 0.f)
                                    : make_float4(0.f, 0.f, 0.f, 0.f);
        else         nxt = P4[(d + 1) * 4 + c];
        float4 o;
        o.x = ppush * prev.x + ppop * nxt.x + pnoop * cur.x;
        o.y = ppush * prev.y + ppop * nxt.y + pnoop * cur.y;
        o.z = ppush * prev.z + ppop * nxt.z + pnoop * cur.z;
        o.w = ppush * prev.w + ppop * nxt.w + pnoop * cur.w;
        if (d == 0) { o.x += pv.x; o.y += pv.y; o.z += pv.z; o.w += pv.w; }
        Q4[d * 4 + c] = o;
        prev = cur; cur = nxt;
    }
}

__global__ __launch_bounds__(256, 2)
void stackrnn_kernel(const int* __restrict__ x, float* __restrict__ out)
{
    __shared__ __align__(16) int   sTok[SEQ];
    __shared__ __align__(16) float sStack[2][1024];   // [ping][64*16]
    __shared__ __align__(16) float sSt[4][64];        // raw state exps
    __shared__ __align__(16) float sZs[4][16];        // state Z partials
    __shared__ __align__(16) float sTop[4][16];       // raw top~
    __shared__ __align__(16) float sZmP[4][8];        // mem Z partials
    __shared__ __align__(16) float sPr[2][20];        // raw probs

    const int tid  = threadIdx.x;
    const int wid  = tid >> 5;
    const int lane = tid & 31;
    const int b    = blockIdx.x;

    // ---- one-time setup ----
    for (int i = tid; i < SEQ; i += 256) sTok[i] = x[(size_t)b * SEQ + i];
    for (int i = tid; i < 1024; i += 256) sStack[0][i] = ((i & 15) == 0) ? 1.f : 0.f;
    if (tid < 64) sSt[0][tid] = 0.f;
    if (tid < 16) sZs[0][tid] = 0.0625f;
    if (tid < 16) sTop[0][tid] = (tid == 0) ? 1.f : 0.f;
    if (tid < 8)  sZmP[0][tid] = (tid == 0) ? 1.f : 0.f;
    if (tid < 20) sPr[0][tid] = (tid == 1) ? 1.f : 0.f;   // noop=1

    // ---- roles ----
    const bool isState  = (wid < 2);
    const bool isMem    = (wid == 2);
    const bool isUpdate = (wid == 3);
    const bool isBuf    = (wid >= 4);
    int mycol;
    if (isState)       mycol = wid * 32 + lane;
    else if (isMem)    mycol = 64 + (lane < 18 ? lane : 0);
    else if (isUpdate) mycol = 0;
    else               mycol = 82 + (wid - 4) * 32 + lane;

    ull W[40];
    float cn = 0.f;
    if (!isUpdate) {
        cn = g_c[mycol];
#pragma unroll
        for (int k = 0; k < 40; k++)
            W[k] = pack2(g_CW[(2 * k) * NOUT + mycol], g_CW[(2 * k + 1) * NOUT + mycol]);
    }
    __syncthreads();

    if (isBuf) {
        // =================== buffer-logit warps, lagged <=3 ===================
        const size_t outB = (size_t)b * (SEQ * 128);
        float baseNext = cn + g_E[sTok[0] * NOUT + mycol];
        for (int t = 0; t < SEQ; t++) {
            const int sCur = t & 3;
            BAR_SYNC(2 + sCur, 256);          // wait slot ready

            const ulonglong2* ZS = (const ulonglong2*)sZs[sCur];
            ulonglong2 z0 = ZS[0], z1 = ZS[1], z2 = ZS[2], z3 = ZS[3];
            ull zz = fadd2(fadd2(fadd2(z0.x, z0.y), fadd2(z1.x, z1.y)),
                           fadd2(fadd2(z2.x, z2.y), fadd2(z3.x, z3.y)));
            const float invZs = __fdividef(1.f, lo2(zz) + hi2(zz));
            const ulonglong2* ZM = (const ulonglong2*)sZmP[sCur];
            ulonglong2 m0 = ZM[0], m1 = ZM[1];
            ull mm = fadd2(fadd2(m0.x, m0.y), fadd2(m1.x, m1.y));
            const float invZm = __fdividef(1.f, lo2(mm) + hi2(mm));
            const float base = baseNext;

            const ulonglong2* S = (const ulonglong2*)sSt[sCur];
            ull a0 = 0, a1 = 0, a2 = 0, a3 = 0;
#pragma unroll
            for (int i = 0; i < 8; i++) {
                ulonglong2 p = S[2 * i], q = S[2 * i + 1];
                a0 = ffma2(W[4 * i + 0], p.x, a0);
                a1 = ffma2(W[4 * i + 1], p.y, a1);
                a2 = ffma2(W[4 * i + 2], q.x, a2);
                a3 = ffma2(W[4 * i + 3], q.y, a3);
            }
            const ulonglong2* T = (const ulonglong2*)sTop[sCur];
            ulonglong2 t0 = T[0], t1 = T[1], t2 = T[2], t3 = T[3];
            ull u0 = ffma2(W[32], t0.x, 0ULL), u1 = ffma2(W[33], t0.y, 0ULL);
            ull u2 = ffma2(W[34], t1.x, 0ULL), u3 = ffma2(W[35], t1.y, 0ULL);
            u0 = ffma2(W[36], t2.x, u0);  u1 = ffma2(W[37], t2.y, u1);
            u2 = ffma2(W[38], t3.x, u2);  u3 = ffma2(W[39], t3.y, u3);

            ull A = fadd2(fadd2(a0, a1), fadd2(a2, a3));
            ull U = fadd2(fadd2(u0, u1), fadd2(u2, u3));
            out[outB + (size_t)t * 128 + (mycol - 82)] =
                base + invZs * (lo2(A) + hi2(A)) + invZm * (lo2(U) + hi2(U));

            if (t + 1 < SEQ)
                baseNext = cn + g_E[sTok[t + 1] * NOUT + mycol];
            BAR_ARRIVE(6 + sCur, 256);        // release slot
        }
    } else {
        // =================== recurrence warps ===================
        float h0 = 0.f, h1 = 0.f, h2 = 0.f;
        float topc = 0.f;
        float cE0 = 0.f, cE1 = 1.f, cZp = 0.125f;
        if (isMem && lane == 0) { h0 = h1 = h2 = 1.f; topc = 1.f; }

        float baseNext = 0.f;
        if (!isUpdate) baseNext = cn + g_E[sTok[0] * NOUT + mycol];

        BAR_ARRIVE(2 + 0, 256);               // slot 0 (initial state) ready

        for (int t = 0; t < SEQ; t++) {
            const int sCur  = t & 3;
            const int sNext = (t + 1) & 3;
            const int ping  = t & 1;
            if (t >= 3) BAR_SYNC(6 + sNext, 256);   // B freed slot we rewrite

            if (isUpdate) {
                stack_update(sPr[ping], sZmP[sCur],
                             sStack[ping], sStack[ping ^ 1], lane);
            } else {
                // mem pre-dot: finish deferred Z + head rows (overlaps dot loads)
                if (isMem) {
                    float Zp = cZp;
                    Zp += __shfl_xor_sync(0xffffffffu, Zp, 4);
                    Zp += __shfl_xor_sync(0xffffffffu, Zp, 8);
                    Zp += __shfl_xor_sync(0xffffffffu, Zp, 16);
                    float izp = __fdividef(1.f, Zp);
                    float nh0 = topc * izp;
                    float nh1 = ((Zp - cE0 - cE1) * h0 + cE0 * h2 + cE1 * h1) * izp;
                    float s1 = 0.f, s2 = 0.f, s3 = 0.f;
                    const float* SB = sStack[ping];
                    if (lane < 16) { s1 = SB[16 + lane]; s2 = SB[32 + lane]; s3 = SB[48 + lane]; }
                    float nh2 = ((Zp - cE0 - cE1) * s1 + cE0 * s3 + cE1 * s2) * izp;
                    h0 = nh0; h1 = nh1; h2 = nh2;
                }

                const ulonglong2* ZS = (const ulonglong2*)sZs[sCur];
                ulonglong2 z0 = ZS[0], z1 = ZS[1], z2 = ZS[2], z3 = ZS[3];
                ull zz = fadd2(fadd2(fadd2(z0.x, z0.y), fadd2(z1.x, z1.y)),
                               fadd2(fadd2(z2.x, z2.y), fadd2(z3.x, z3.y)));
                const float invZs = __fdividef(1.f, lo2(zz) + hi2(zz));
                const ulonglong2* ZM = (const ulonglong2*)sZmP[sCur];
                ulonglong2 m0 = ZM[0], m1 = ZM[1];
                ull mm = fadd2(fadd2(m0.x, m0.y), fadd2(m1.x, m1.y));
                const float invZm = __fdividef(1.f, lo2(mm) + hi2(mm));
                const float base = baseNext;

                const ulonglong2* S = (const ulonglong2*)sSt[sCur];
                ull a0 = 0, a1 = 0, a2 = 0, a3 = 0;
#pragma unroll
                for (int i = 0; i < 8; i++) {
                    ulonglong2 p = S[2 * i], q = S[2 * i + 1];
                    a0 = ffma2(W[4 * i + 0], p.x, a0);
                    a1 = ffma2(W[4 * i + 1], p.y, a1);
                    a2 = ffma2(W[4 * i + 2], q.x, a2);
                    a3 = ffma2(W[4 * i + 3], q.y, a3);
                }
                const ulonglong2* T = (const ulonglong2*)sTop[sCur];
                ulonglong2 t0 = T[0], t1 = T[1], t2 = T[2], t3 = T[3];
                ull u0 = ffma2(W[32], t0.x, 0ULL), u1 = ffma2(W[33], t0.y, 0ULL);
                ull u2 = ffma2(W[34], t1.x, 0ULL), u3 = ffma2(W[35], t1.y, 0ULL);
                u0 = ffma2(W[36], t2.x, u0);  u1 = ffma2(W[37], t2.y, u1);
                u2 = ffma2(W[38], t3.x, u2);  u3 = ffma2(W[39], t3.y, u3);

                ull A = fadd2(fadd2(a0, a1), fadd2(a2, a3));
                ull U = fadd2(fadd2(u0, u1), fadd2(u2, u3));
                const float r = base + invZs * (lo2(A) + hi2(A)) + invZm * (lo2(U) + hi2(U));

                if (t + 1 < SEQ)
                    baseNext = cn + g_E[sTok[t + 1] * NOUT + mycol];

                if (isState) {
                    float e = __expf(r);
                    sSt[sNext][mycol] = e;
                    float ps = e;
                    ps += __shfl_xor_sync(0xffffffffu, ps, 1);
                    ps += __shfl_xor_sync(0xffffffffu, ps, 2);
                    if ((lane & 3) == 0)
                        sZs[sNext][wid * 8 + (lane >> 2)] = ps;
                } else {  // mem
                    float e = (lane < 18) ? __expf(r) : 0.f;
                    float E0 = __shfl_sync(0xffffffffu, e, 0);
                    float E1 = __shfl_sync(0xffffffffu, e, 1);
                    float ep = __shfl_sync(0xffffffffu, e, 2 + (lane & 15));
                    float topn = E1 * h0 + E0 * h1 + ep;          // raw, scale Zt
                    if (lane < 16) sTop[sNext][lane] = topn;
                    int pidx = (lane < 2) ? lane : lane + 2;
                    if (lane < 18) sPr[ping ^ 1][pidx] = e;
                    float pz = e;
                    pz += __shfl_xor_sync(0xffffffffu, pz, 1);
                    pz += __shfl_xor_sync(0xffffffffu, pz, 2);
                    if ((lane & 3) == 0) sZmP[sNext][lane >> 2] = pz;
                    topc = topn; cE0 = E0; cE1 = E1; cZp = pz;
                }
            }
            BAR_ARRIVE(2 + sNext, 256);   // slot sNext ready for B
            BAR_SYNC(1, 128);             // recurrence-internal step barrier
        }

        // epilogue: apply probs_{S-1} -> stack_S (sPr ping 0, sZmP slot 0)
        if (isUpdate) {
            stack_update(sPr[0], sZmP[0], sStack[0], sStack[1], lane);
        }
    }
    __syncthreads();

    // ---- finals ----
    const size_t fsOff = (size_t)B_TOT * SEQ * 128;
    const size_t stOff = fsOff + (size_t)B_TOT * 64 * 16;
    for (int i = tid; i < 1024; i += 256)
        out[fsOff + (size_t)b * 1024 + i] = sStack[1][i];
    if (tid < 64) {
        float zs = 0.f;
        for (int j = 0; j < 16; j++) zs += sZs[0][j];      // slot 0
        out[stOff + (size_t)b * 64 + tid] =
            sSt[0][tid] * __fdividef(1.f, zs);             // slot 0
    }
}

extern "C" void kernel_launch(void* const* d_in, const int* in_sizes, int n_in,
                              void* d_out, int out_size)
{
    const int*   x       = (const int*)  d_in[0];
    const float* embed   = (const float*)d_in[1];
    const float* w_state = (const float*)d_in[2];
    const float* b_state = (const float*)d_in[3];
    const float* w_top   = (const float*)d_in[4];
    const float* b_top   = (const float*)d_in[5];
    const float* w_mem   = (const float*)d_in[6];
    const float* b_mem   = (const float*)d_in[7];
    const float* w_buf   = (const float*)d_in[8];
    const float* b_buf   = (const float*)d_in[9];
    const float* w_st    = (const float*)d_in[10];
    const float* b_st    = (const float*)d_in[11];
    float* out = (float*)d_out;

    precompute_kernel<<<NOUT, 448>>>(embed, w_state, b_state, w_top, b_top,
                                     w_mem, b_mem, w_buf, b_buf, w_st, b_st);

    stackrnn_kernel<<<B_TOT, 256>>>(x, out);
}

// round 17
// speedup vs baseline: 1.0984x; 1.0300x over previous
#include <cuda_runtime.h>
#include <cuda_bf16.h>
#include <cstdint>

// ---------------------------------------------------------------------------
// StackRNN v17 = v12 (best: 740.1us) with ONE surgical change: state-Z
// partials reduced depth-2 -> depth-4. sZs shrinks 16 -> 4 floats per
// (slot,g); consumers read ONE LDS.128 (+3 adds) instead of four (+7 adds).
// Producers (state warps) add 2 shuffles to a latency-hidden tail.
// Everything else byte-identical to v12.
//
// Group A (warps 0-7, 256 thr): 4 state + 2 mem + 2 update warps. One
//   bar.sync(1,256) per step. Writes per-step slots into a DEPTH-4 ring.
// Group B (warps 8-15, 256 thr): buffer-logit warps, lag <=3 steps behind.
//   Per slot s: ready barrier id 2+s (A arrives, B syncs), free id 6+s.
// ---------------------------------------------------------------------------

#define NOUT 210
#define B_TOT 256
#define SEQ 1024
#define NTHREADS 512

#define BAR_SYNC(id, cnt)   asm volatile("bar.sync %0, %1;"   :: "r"(id), "r"(cnt) : "memory")
#define BAR_ARRIVE(id, cnt) asm volatile("bar.arrive %0, %1;" :: "r"(id), "r"(cnt) : "memory")

typedef unsigned long long ull;

__device__ __forceinline__ ull ffma2(ull a, ull b, ull c) {
    ull d; asm("fma.rn.f32x2 %0,%1,%2,%3;" : "=l"(d) : "l"(a), "l"(b), "l"(c)); return d;
}
__device__ __forceinline__ ull fadd2(ull a, ull b) {
    ull d; asm("add.rn.f32x2 %0,%1,%2;" : "=l"(d) : "l"(a), "l"(b)); return d;
}
__device__ __forceinline__ ull pack2(float lo, float hi) {
    ull d; asm("mov.b64 %0,{%1,%2};" : "=l"(d) : "f"(lo), "f"(hi)); return d;
}
__device__ __forceinline__ float lo2(ull v) { return __uint_as_float((unsigned)v); }
__device__ __forceinline__ float hi2(ull v) { return __uint_as_float((unsigned)(v >> 32)); }

__device__ __align__(16) float g_E[128 * NOUT];
__device__ __align__(16) float g_CW[80 * NOUT];
__device__ __align__(16) float g_c[NOUT];

// ---------------- fast precompute (bench-verified in v12) ----------------
__global__ void precompute_kernel(
    const float* __restrict__ embed,
    const float* __restrict__ w_state, const float* __restrict__ b_state,
    const float* __restrict__ w_top,   const float* __restrict__ b_top,
    const float* __restrict__ w_mem,   const float* __restrict__ b_mem,
    const float* __restrict__ w_buf,   const float* __restrict__ b_buf,
    const float* __restrict__ w_st,    const float* __restrict__ b_st)
{
    __shared__ __align__(16) float wcol[768];
    int n = blockIdx.x;
    const float* W; const float* bias; int N, col;
    if (n < 64)       { W = w_st;  bias = b_st;  N = 64;  col = n; }
    else if (n < 82)  { W = w_mem; bias = b_mem; N = 18;  col = n - 64; }
    else              { W = w_buf; bias = b_buf; N = 128; col = n - 82; }

    const int tid = threadIdx.x;
    for (int i = tid; i < 768; i += 448) wcol[i] = W[i * N + col];
    __syncthreads();

    float sp = 0.f;
    if (tid < 256) {
        int row = tid >> 1, half = tid & 1;
        const float4* er = (const float4*)(embed + row * 256 + half * 128);
        const float4* wc = (const float4*)(wcol + half * 128);
        float s0 = 0.f, s1 = 0.f, s2 = 0.f, s3 = 0.f;
#pragma unroll 8
        for (int h = 0; h < 32; h++) {
            float4 e = er[h], w4 = wc[h];
            s0 += e.x * w4.x; s1 += e.y * w4.y;
            s2 += e.z * w4.z; s3 += e.w * w4.w;
        }
        sp = (s0 + s1) + (s2 + s3);
    } else if (tid < 384) {
        int r = (tid - 256) >> 1, half = tid & 1;
        const float4* wr = (const float4*)(w_state + r * 256 + half * 128);
        const float4* wc = (const float4*)(wcol + 256 + half * 128);
        float s0 = 0.f, s1 = 0.f, s2 = 0.f, s3 = 0.f;
#pragma unroll 8
        for (int h = 0; h < 32; h++) {
            float4 e = wr[h], w4 = wc[h];
            s0 += e.x * w4.x; s1 += e.y * w4.y;
            s2 += e.z * w4.z; s3 += e.w * w4.w;
        }
        sp = (s0 + s1) + (s2 + s3);
    } else if (tid < 416) {
        int r = (tid - 384) >> 1, half = tid & 1;
        const float4* wr = (const float4*)(w_top + r * 256 + half * 128);
        const float4* wc = (const float4*)(wcol + 512 + half * 128);
        float s0 = 0.f, s1 = 0.f, s2 = 0.f, s3 = 0.f;
#pragma unroll 8
        for (int h = 0; h < 32; h++) {
            float4 e = wr[h], w4 = wc[h];
            s0 += e.x * w4.x; s1 += e.y * w4.y;
            s2 += e.z * w4.z; s3 += e.w * w4.w;
        }
        sp = (s0 + s1) + (s2 + s3);
    } else {
        int lane = tid - 416;
        const float4* bs = (const float4*)b_state;
        const float4* bt = (const float4*)b_top;
        const float4* wc = (const float4*)(wcol + 256);
#pragma unroll
        for (int j = 0; j < 4; j++) {
            int k = lane + j * 32;
            float4 b4 = (k < 64) ? bs[k] : bt[k - 64];
            float4 w4 = wc[k];
            sp += b4.x * w4.x + b4.y * w4.y + b4.z * w4.z + b4.w * w4.w;
        }
        float t = sp;
        for (int o = 16; o; o >>= 1) t += __shfl_xor_sync(0xffffffffu, t, o);
        if (lane == 0) g_c[n] = t + bias[col];
    }

    float pair = sp + __shfl_xor_sync(0xffffffffu, sp, 1);
    if ((tid & 1) == 0) {
        if (tid < 256)      g_E[(tid >> 1) * NOUT + n] = pair;
        else if (tid < 384) g_CW[((tid - 256) >> 1) * NOUT + n] = pair;
        else if (tid < 416) g_CW[(64 + ((tid - 384) >> 1)) * NOUT + n] = pair;
    }
}

// Shared floats:
//   sE     @ 0     : 26880            [tok][n]
//   sTok   @ 26880 : 2048 ints        [g][t]
//   sStack @ 28928 : [ping][g][64][16] = 4096   (depth 2, A-only)
//   sSt    @ 33024 : [slot][g][64] = 512        raw state exps (depth 4)
//   sZs    @ 33536 : [slot][g][4]  = 32         state Z partials (depth-4 reduce)
//   sTop   @ 33568 : [slot][g][16] = 128        raw top~ (depth 4)
//   sZmP   @ 33696 : [slot][g][8]  = 64         mem Z partials (depth 4)
//   sPr    @ 33760 : [ping][g][20] = 80         raw probs (depth 2, A-only)
#define SMEM_FLOATS 33840

__device__ __forceinline__ void stack_update(const float* pr, const float* zmp,
                                             const float* P, float* Q, int lane)
{
    float pe0 = pr[0], pe1 = pr[1];
    float4 za = *(const float4*)zmp;
    float4 zb = *(const float4*)(zmp + 4);
    float Zr = ((za.x + za.y) + (za.z + za.w)) + ((zb.x + zb.y) + (zb.z + zb.w));
    float iz = __fdividef(1.f, Zr);
    float ppop  = pe0 * iz;
    float pnoop = pe1 * iz;
    float ppush = (Zr - pe0 - pe1) * iz;
    const int c = lane & 3;
    const int d0 = (lane >> 2) * 8;
    float4 pv = ((const float4*)(pr + 4))[c];
    pv.x *= iz; pv.y *= iz; pv.z *= iz; pv.w *= iz;

    const float4* P4 = (const float4*)P;
    float4*       Q4 = (float4*)Q;
    float4 prev = (d0 == 0) ? make_float4(0.f, 0.f, 0.f, 0.f) : P4[(d0 - 1) * 4 + c];
    float4 cur  = P4[d0 * 4 + c];
#pragma unroll
    for (int i = 0; i < 8; i++) {
        int d = d0 + i;
        float4 nxt;
        if (d == 63) nxt = (c == 0) ? make_float4(1.f, 0.f, 0.f, 0.f)
                                    : make_float4(0.f, 0.f, 0.f, 0.f);
        else         nxt = P4[(d + 1) * 4 + c];
        float4 o;
        o.x = ppush * prev.x + ppop * nxt.x + pnoop * cur.x;
        o.y = ppush * prev.y + ppop * nxt.y + pnoop * cur.y;
        o.z = ppush * prev.z + ppop * nxt.z + pnoop * cur.z;
        o.w = ppush * prev.w + ppop * nxt.w + pnoop * cur.w;
        if (d == 0) { o.x += pv.x; o.y += pv.y; o.z += pv.z; o.w += pv.w; }
        Q4[d * 4 + c] = o;
        prev = cur; cur = nxt;
    }
}

__global__ __launch_bounds__(NTHREADS, 1)
void stackrnn_kernel(const int* __restrict__ x, float* __restrict__ out)
{
    extern __shared__ float sm[];
    float* sE     = sm;
    int*   sTok   = (int*)(sm + 26880);
    float* sStack = sm + 28928;
    float* sSt    = sm + 33024;
    float* sZs    = sm + 33536;
    float* sTop   = sm + 33568;
    float* sZmP   = sm + 33696;
    float* sPr    = sm + 33760;

    const int tid  = threadIdx.x;
    const int wid  = tid >> 5;
    const int lane = tid & 31;
    const int b0   = blockIdx.x * 2;

    // ---- one-time setup ----
    {
        const float4* src = (const float4*)g_E;
        float4* dst = (float4*)sE;
        for (int i = tid; i < (128 * NOUT) / 4; i += NTHREADS) dst[i] = src[i];
    }
    for (int i = tid; i < 2 * SEQ; i += NTHREADS) {
        int g = i >> 10, r = i & 1023;
        sTok[i] = x[(size_t)(b0 + g) * SEQ + r];
    }
    for (int i = tid; i < 2048; i += NTHREADS) sStack[i] = ((i & 15) == 0) ? 1.f : 0.f;
    if (tid < 128) sSt[tid] = 0.f;                            // slot 0
    if (tid < 8)   sZs[tid]  = 0.25f;                         // slot 0: sums to 1
    if (tid < 32)  sTop[tid] = (tid == 0 || tid == 16) ? 1.f : 0.f;
    if (tid < 16)  sZmP[tid] = (tid == 0 || tid == 8) ? 1.f : 0.f;
    if (tid < 40)  sPr[tid]  = (tid == 1 || tid == 21) ? 1.f : 0.f;  // noop=1

    // ---- roles ----
    const bool isState  = (wid < 4);
    const bool isMem    = (wid == 4 || wid == 5);
    const bool isUpdate = (wid == 6 || wid == 7);
    const bool isBuf    = (wid >= 8);
    int g, mycol;
    if (isState)       { g = wid >> 1;  mycol = (wid & 1) * 32 + lane; }
    else if (isMem)    { g = wid - 4;   mycol = 64 + (lane < 18 ? lane : 0); }
    else if (isUpdate) { g = wid - 6;   mycol = 0; }
    else               { int idx = tid - 256; g = idx >> 7; mycol = 82 + (idx & 127); }

    ull W[40];
    float cn = 0.f;
    if (!isUpdate) {
        cn = g_c[mycol];
#pragma unroll
        for (int k = 0; k < 40; k++)
            W[k] = pack2(g_CW[(2 * k) * NOUT + mycol], g_CW[(2 * k + 1) * NOUT + mycol]);
    }
    __syncthreads();

    if (isBuf) {
        // =================== GROUP B: buffer logits, lagged ===================
        const size_t outB = (size_t)(b0 + g) * (SEQ * 128);
        float baseNext = cn + sE[sTok[g * SEQ] * NOUT + mycol];
        for (int t = 0; t < SEQ; t++) {
            const int sCur = t & 3;
            BAR_SYNC(2 + sCur, 512);          // wait slot ready

            ulonglong2 zp = *(const ulonglong2*)(sZs + sCur * 8 + g * 4);
            ull zz = fadd2(zp.x, zp.y);
            const float invZs = __fdividef(1.f, lo2(zz) + hi2(zz));
            const ulonglong2* ZM = (const ulonglong2*)(sZmP + sCur * 16 + g * 8);
            ulonglong2 m0 = ZM[0], m1 = ZM[1];
            ull mm = fadd2(fadd2(m0.x, m0.y), fadd2(m1.x, m1.y));
            const float invZm = __fdividef(1.f, lo2(mm) + hi2(mm));
            const float base = baseNext;

            const ulonglong2* S = (const ulonglong2*)(sSt + sCur * 128 + g * 64);
            ull a0 = 0, a1 = 0, a2 = 0, a3 = 0;
#pragma unroll
            for (int i = 0; i < 8; i++) {
                ulonglong2 p = S[2 * i], q = S[2 * i + 1];
                a0 = ffma2(W[4 * i + 0], p.x, a0);
                a1 = ffma2(W[4 * i + 1], p.y, a1);
                a2 = ffma2(W[4 * i + 2], q.x, a2);
                a3 = ffma2(W[4 * i + 3], q.y, a3);
            }
            const ulonglong2* T = (const ulonglong2*)(sTop + sCur * 32 + g * 16);
            ulonglong2 t0 = T[0], t1 = T[1], t2 = T[2], t3 = T[3];
            ull u0 = ffma2(W[32], t0.x, 0ULL), u1 = ffma2(W[33], t0.y, 0ULL);
            ull u2 = ffma2(W[34], t1.x, 0ULL), u3 = ffma2(W[35], t1.y, 0ULL);
            u0 = ffma2(W[36], t2.x, u0);  u1 = ffma2(W[37], t2.y, u1);
            u2 = ffma2(W[38], t3.x, u2);  u3 = ffma2(W[39], t3.y, u3);

            ull A = fadd2(fadd2(a0, a1), fadd2(a2, a3));
            ull U = fadd2(fadd2(u0, u1), fadd2(u2, u3));
            const float r = base + invZs * (lo2(A) + hi2(A)) + invZm * (lo2(U) + hi2(U));
            out[outB + (size_t)t * 128 + (mycol - 82)] = r;

            if (t + 1 < SEQ)
                baseNext = cn + sE[sTok[g * SEQ + t + 1] * NOUT + mycol];
            BAR_ARRIVE(6 + sCur, 512);        // release slot
        }
    } else {
        // =================== GROUP A: recurrence ===================
        // mem-warp carried regs (lanes 0..15 hold vocab component v=lane)
        float h0 = 0.f, h1 = 0.f, h2 = 0.f;      // normalized rows of current stack
        float topc = 0.f;                         // raw row0 of next stack
        float cE0 = 0.f, cE1 = 1.f, cZp = 0.125f; // probs_{-1}=noop; Z partial
        if (isMem && lane == 0) { h0 = h1 = h2 = 1.f; topc = 1.f; }

        float baseNext = 0.f;
        if (!isUpdate) baseNext = cn + sE[sTok[g * SEQ] * NOUT + mycol];

        BAR_ARRIVE(2 + 0, 512);                   // slot 0 (initial state) ready

        for (int t = 0; t < SEQ; t++) {
            const int sCur  = t & 3;
            const int sNext = (t + 1) & 3;
            const int ping  = t & 1;
            if (t >= 3) BAR_SYNC(6 + sNext, 512); // wait B freed the slot we rewrite

            if (isUpdate) {
                stack_update(sPr + ping * 40 + g * 20, sZmP + sCur * 16 + g * 8,
                             sStack + ping * 2048 + g * 1024,
                             sStack + (ping ^ 1) * 2048 + g * 1024, lane);
            } else {
                // mem pre-dot: finish deferred Z + head rows (overlaps dot loads)
                if (isMem) {
                    float Zp = cZp;
                    Zp += __shfl_xor_sync(0xffffffffu, Zp, 4);
                    Zp += __shfl_xor_sync(0xffffffffu, Zp, 8);
                    Zp += __shfl_xor_sync(0xffffffffu, Zp, 16);
                    float izp = __fdividef(1.f, Zp);
                    float nh0 = topc * izp;
                    float nh1 = ((Zp - cE0 - cE1) * h0 + cE0 * h2 + cE1 * h1) * izp;
                    float s1 = 0.f, s2 = 0.f, s3 = 0.f;
                    const float* SB = sStack + ping * 2048 + g * 1024;
                    if (lane < 16) { s1 = SB[16 + lane]; s2 = SB[32 + lane]; s3 = SB[48 + lane]; }
                    float nh2 = ((Zp - cE0 - cE1) * s1 + cE0 * s3 + cE1 * s2) * izp;
                    h0 = nh0; h1 = nh1; h2 = nh2;
                }

                ulonglong2 zp2 = *(const ulonglong2*)(sZs + sCur * 8 + g * 4);
                ull zzp = fadd2(zp2.x, zp2.y);
                const float invZs = __fdividef(1.f, lo2(zzp) + hi2(zzp));
                const ulonglong2* ZM = (const ulonglong2*)(sZmP + sCur * 16 + g * 8);
                ulonglong2 m0 = ZM[0], m1 = ZM[1];
                ull mm = fadd2(fadd2(m0.x, m0.y), fadd2(m1.x, m1.y));
                const float invZm = __fdividef(1.f, lo2(mm) + hi2(mm));
                const float base = baseNext;

                const ulonglong2* S = (const ulonglong2*)(sSt + sCur * 128 + g * 64);
                ull a0 = 0, a1 = 0, a2 = 0, a3 = 0;
#pragma unroll
                for (int i = 0; i < 8; i++) {
                    ulonglong2 p = S[2 * i], q = S[2 * i + 1];
                    a0 = ffma2(W[4 * i + 0], p.x, a0);
                    a1 = ffma2(W[4 * i + 1], p.y, a1);
                    a2 = ffma2(W[4 * i + 2], q.x, a2);
                    a3 = ffma2(W[4 * i + 3], q.y, a3);
                }
                const ulonglong2* T = (const ulonglong2*)(sTop + sCur * 32 + g * 16);
                ulonglong2 t0 = T[0], t1 = T[1], t2 = T[2], t3 = T[3];
                ull u0 = ffma2(W[32], t0.x, 0ULL), u1 = ffma2(W[33], t0.y, 0ULL);
                ull u2 = ffma2(W[34], t1.x, 0ULL), u3 = ffma2(W[35], t1.y, 0ULL);
                u0 = ffma2(W[36], t2.x, u0);  u1 = ffma2(W[37], t2.y, u1);
                u2 = ffma2(W[38], t3.x, u2);  u3 = ffma2(W[39], t3.y, u3);

                ull A = fadd2(fadd2(a0, a1), fadd2(a2, a3));
                ull U = fadd2(fadd2(u0, u1), fadd2(u2, u3));
                const float r = base + invZs * (lo2(A) + hi2(A)) + invZm * (lo2(U) + hi2(U));

                if (t + 1 < SEQ)
                    baseNext = cn + sE[sTok[g * SEQ + t + 1] * NOUT + mycol];

                if (isState) {
                    float e = __expf(r);
                    sSt[sNext * 128 + g * 64 + mycol] = e;
                    float ps = e;
                    ps += __shfl_xor_sync(0xffffffffu, ps, 1);
                    ps += __shfl_xor_sync(0xffffffffu, ps, 2);
                    ps += __shfl_xor_sync(0xffffffffu, ps, 4);
                    ps += __shfl_xor_sync(0xffffffffu, ps, 8);
                    if ((lane & 15) == 0)
                        sZs[sNext * 8 + g * 4 + (wid & 1) * 2 + (lane >> 4)] = ps;
                } else {  // mem
                    float e = (lane < 18) ? __expf(r) : 0.f;
                    float E0 = __shfl_sync(0xffffffffu, e, 0);
                    float E1 = __shfl_sync(0xffffffffu, e, 1);
                    float ep = __shfl_sync(0xffffffffu, e, 2 + (lane & 15));
                    float topn = E1 * h0 + E0 * h1 + ep;          // raw, scale Zt
                    if (lane < 16) sTop[sNext * 32 + g * 16 + lane] = topn;
                    int pidx = (lane < 2) ? lane : lane + 2;
                    if (lane < 18) sPr[(ping ^ 1) * 40 + g * 20 + pidx] = e;
                    float pz = e;
                    pz += __shfl_xor_sync(0xffffffffu, pz, 1);
                    pz += __shfl_xor_sync(0xffffffffu, pz, 2);
                    if ((lane & 3) == 0) sZmP[sNext * 16 + g * 8 + (lane >> 2)] = pz;
                    topc = topn; cE0 = E0; cE1 = E1; cZp = pz;
                }
            }
            BAR_ARRIVE(2 + sNext, 512);   // slot sNext ready for B (after own writes)
            BAR_SYNC(1, 256);             // A-internal step barrier
        }

        // epilogue: apply probs_{S-1} -> stack_S  (probs in sPr[0], Z in slot 0)
        if (isUpdate) {
            stack_update(sPr + 0 * 40 + g * 20, sZmP + 0 * 16 + g * 8,
                         sStack + 0 * 2048 + g * 1024,
                         sStack + 1 * 2048 + g * 1024, lane);
        }
    }
    __syncthreads();

    // ---- finals ----
    const size_t fsOff = (size_t)B_TOT * SEQ * 128;
    const size_t stOff = fsOff + (size_t)B_TOT * 64 * 16;
    for (int i = tid; i < 2048; i += NTHREADS) {
        int gg = i >> 10, r = i & 1023;
        out[fsOff + (size_t)(b0 + gg) * 1024 + r] = sStack[2048 + i];
    }
    if (tid < 128) {
        int gg = tid >> 6;
        float zs = sZs[gg * 4] + sZs[gg * 4 + 1] + sZs[gg * 4 + 2] + sZs[gg * 4 + 3];
        out[stOff + (size_t)(b0 + gg) * 64 + (tid & 63)] =
            sSt[tid] * __fdividef(1.f, zs);                    // slot 0
    }
}

extern "C" void kernel_launch(void* const* d_in, const int* in_sizes, int n_in,
                              void* d_out, int out_size)
{
    const int*   x       = (const int*)  d_in[0];
    const float* embed   = (const float*)d_in[1];
    const float* w_state = (const float*)d_in[2];
    const float* b_state = (const float*)d_in[3];
    const float* w_top   = (const float*)d_in[4];
    const float* b_top   = (const float*)d_in[5];
    const float* w_mem   = (const float*)d_in[6];
    const float* b_mem   = (const float*)d_in[7];
    const float* w_buf   = (const float*)d_in[8];
    const float* b_buf   = (const float*)d_in[9];
    const float* w_st    = (const float*)d_in[10];
    const float* b_st    = (const float*)d_in[11];
    float* out = (float*)d_out;

    precompute_kernel<<<NOUT, 448>>>(embed, w_state, b_state, w_top, b_top,
                                     w_mem, b_mem, w_buf, b_buf, w_st, b_st);

    cudaFuncSetAttribute(stackrnn_kernel,
                         cudaFuncAttributeMaxDynamicSharedMemorySize,
                         SMEM_FLOATS * sizeof(float));
    stackrnn_kernel<<<B_TOT / 2, NTHREADS, SMEM_FLOATS * sizeof(float)>>>(x, out);
}